// round 14
// baseline (speedup 1.0000x reference)
#include <cuda_runtime.h>

// CanonConv: out[b,t,c] = x[b,t,c] + bias[c] + sum_{k=0..3} w[c,k] * x[b, t+k-3, c]
// x: (B=4, T=4096, C=2048) fp32, row-major. weight: (C,4). bias: (C,).
//
// R1:  S=64: occ 40%, DRAM 57%, 50.8us.
// R2:  S=32, unroll 8, __stcs: 40.3us.
// R3:  S=16, lb(128,9), default reads: regs 56, occ 49.2%, 38.2us.  <- BEST
// R8:  __ldcs all reads: 43.3us (regression).
// R10: lb(128,10) + fma fold (regs 48): 39.3us (occ>50% + fewer regs -> less
//      load batching; small regression).
// R11: mixed __ldcs/default reads: 43.6us. LAW: any __ldcs on reads regresses.
// R13: R3 config restored verbatim + __ldcg reads (L2-cached, L1-bypass):
//      zero L1 reuse per line, so skip L1 fill to cut L1tex queue work while
//      keeping halo L2 residency (default L2 policy, unlike .cs).

#define BB 4
#define TT 4096
#define CC 2048
#define CV (CC / 4)       // 512 float4 channel-vectors per row
#define S  16             // timesteps per block strip
#define TPB 128           // threads per block (covers 128 cvecs)

__global__ __launch_bounds__(TPB, 9) void canonconv_kernel(
    const float* __restrict__ x,
    const float* __restrict__ w,      // (C, 4)
    const float* __restrict__ bias,   // (C,)
    float* __restrict__ out)
{
    const int cvec = blockIdx.y * TPB + threadIdx.x;   // 0..511
    const int c    = cvec * 4;
    const int b    = blockIdx.z;
    const int t0   = blockIdx.x * S;

    const float4* __restrict__ x4 = reinterpret_cast<const float4*>(x);
    float4* __restrict__ o4       = reinterpret_cast<float4*>(out);

    // per-channel weight rows: wr[j] = (w[c+j,0..3])
    const float4* __restrict__ w4 = reinterpret_cast<const float4*>(w);
    const float4 wr0 = w4[c + 0];
    const float4 wr1 = w4[c + 1];
    const float4 wr2 = w4[c + 2];
    const float4 wr3 = w4[c + 3];
    const float4 bi  = reinterpret_cast<const float4*>(bias)[cvec];

    // max index 4*4096*512 = 8.4M float4s -> fits int
    int idx = (b * TT + t0) * CV + cvec;

    const float4 zero = make_float4(0.f, 0.f, 0.f, 0.f);
    // sliding window: x at t0-3, t0-2, t0-1 (t0 is a multiple of S).
    // .cg: L2-cached (halo reuse preserved), L1 bypassed (no reuse there).
    float4 xm3 = (t0 >= 3) ? __ldcg(&x4[idx - 3 * CV]) : zero;
    float4 xm2 = (t0 >= 2) ? __ldcg(&x4[idx - 2 * CV]) : zero;
    float4 xm1 = (t0 >= 1) ? __ldcg(&x4[idx - 1 * CV]) : zero;

#pragma unroll
    for (int i = 0; i < S; i++) {
        const float4 xc = __ldcg(&x4[idx]);
        float4 r;
        r.x = fmaf(xm3.x, wr0.x, fmaf(xm2.x, wr0.y, fmaf(xm1.x, wr0.z, fmaf(xc.x, wr0.w, xc.x + bi.x))));
        r.y = fmaf(xm3.y, wr1.x, fmaf(xm2.y, wr1.y, fmaf(xm1.y, wr1.z, fmaf(xc.y, wr1.w, xc.y + bi.y))));
        r.z = fmaf(xm3.z, wr2.x, fmaf(xm2.z, wr2.y, fmaf(xm1.z, wr2.z, fmaf(xc.z, wr2.w, xc.z + bi.z))));
        r.w = fmaf(xm3.w, wr3.x, fmaf(xm2.w, wr3.y, fmaf(xm1.w, wr3.z, fmaf(xc.w, wr3.w, xc.w + bi.w))));
        __stcs(&o4[idx], r);   // write-once output: streaming store
        xm3 = xm2; xm2 = xm1; xm1 = xc;
        idx += CV;
    }
}

extern "C" void kernel_launch(void* const* d_in, const int* in_sizes, int n_in,
                              void* d_out, int out_size)
{
    const float* x    = (const float*)d_in[0];
    const float* w    = (const float*)d_in[1];
    const float* bias = (const float*)d_in[2];
    float* out        = (float*)d_out;

    dim3 grid(TT / S, CV / TPB, BB);   // (256, 4, 4) = 4096 CTAs
    dim3 block(TPB);
    canonconv_kernel<<<grid, block>>>(x, w, bias, out);
}

// round 15
// speedup vs baseline: 1.0964x; 1.0964x over previous
#include <cuda_runtime.h>

// CanonConv: out[b,t,c] = x[b,t,c] + bias[c] + sum_{k=0..3} w[c,k] * x[b, t+k-3, c]
// x: (B=4, T=4096, C=2048) fp32, row-major. weight: (C,4). bias: (C,).
//
// CONVERGED CONFIG (R3, measured best, replicated):
//   S=16, TPB=128, __launch_bounds__(128,9), DEFAULT-cached reads, __stcs stores.
//   regs 56, occ 49.2%, DRAM 71.8%, kernel 38.2us (~92% of HBM floor).
//
// Session law (5 failed perturbations): any load-path cache hint (.cs/.cg) or
// reg-diet (fma fold, lb(,10)) drops regs 56->48, which kills ptxas's
// front-batched load MLP -> latency-limited kernel regresses 1-6us. The reg
// "waste" at 56 IS the MLP buffer. occ>~50% also regresses (L1tex queue).

#define BB 4
#define TT 4096
#define CC 2048
#define CV (CC / 4)       // 512 float4 channel-vectors per row
#define S  16             // timesteps per block strip
#define TPB 128           // threads per block (covers 128 cvecs)

__global__ __launch_bounds__(TPB, 9) void canonconv_kernel(
    const float* __restrict__ x,
    const float* __restrict__ w,      // (C, 4)
    const float* __restrict__ bias,   // (C,)
    float* __restrict__ out)
{
    const int cvec = blockIdx.y * TPB + threadIdx.x;   // 0..511
    const int c    = cvec * 4;
    const int b    = blockIdx.z;
    const int t0   = blockIdx.x * S;

    const float4* __restrict__ x4 = reinterpret_cast<const float4*>(x);
    float4* __restrict__ o4       = reinterpret_cast<float4*>(out);

    // per-channel weight rows: wr[j] = (w[c+j,0..3])
    const float4* __restrict__ w4 = reinterpret_cast<const float4*>(w);
    const float4 wr0 = w4[c + 0];
    const float4 wr1 = w4[c + 1];
    const float4 wr2 = w4[c + 2];
    const float4 wr3 = w4[c + 3];
    const float4 bi  = reinterpret_cast<const float4*>(bias)[cvec];

    // max index 4*4096*512 = 8.4M float4s -> fits int
    int idx = (b * TT + t0) * CV + cvec;

    const float4 zero = make_float4(0.f, 0.f, 0.f, 0.f);
    // sliding window: x at t0-3, t0-2, t0-1 (t0 is a multiple of S).
    // Default caching: previous strip's freshest rows -> L2 hits here.
    float4 xm3 = (t0 >= 3) ? x4[idx - 3 * CV] : zero;
    float4 xm2 = (t0 >= 2) ? x4[idx - 2 * CV] : zero;
    float4 xm1 = (t0 >= 1) ? x4[idx - 1 * CV] : zero;

#pragma unroll
    for (int i = 0; i < S; i++) {
        const float4 xc = x4[idx];
        float4 r;
        r.x = fmaf(xm3.x, wr0.x, fmaf(xm2.x, wr0.y, fmaf(xm1.x, wr0.z, fmaf(xc.x, wr0.w, xc.x + bi.x))));
        r.y = fmaf(xm3.y, wr1.x, fmaf(xm2.y, wr1.y, fmaf(xm1.y, wr1.z, fmaf(xc.y, wr1.w, xc.y + bi.y))));
        r.z = fmaf(xm3.z, wr2.x, fmaf(xm2.z, wr2.y, fmaf(xm1.z, wr2.z, fmaf(xc.z, wr2.w, xc.z + bi.z))));
        r.w = fmaf(xm3.w, wr3.x, fmaf(xm2.w, wr3.y, fmaf(xm1.w, wr3.z, fmaf(xc.w, wr3.w, xc.w + bi.w))));
        __stcs(&o4[idx], r);   // write-once output: streaming store
        xm3 = xm2; xm2 = xm1; xm1 = xc;
        idx += CV;
    }
}

extern "C" void kernel_launch(void* const* d_in, const int* in_sizes, int n_in,
                              void* d_out, int out_size)
{
    const float* x    = (const float*)d_in[0];
    const float* w    = (const float*)d_in[1];
    const float* bias = (const float*)d_in[2];
    float* out        = (float*)d_out;

    dim3 grid(TT / S, CV / TPB, BB);   // (256, 4, 4) = 4096 CTAs
    dim3 block(TPB);
    canonconv_kernel<<<grid, block>>>(x, w, bias, out);
}

// round 17
// speedup vs baseline: 1.1421x; 1.0417x over previous
#include <cuda_runtime.h>

// CanonConv: out[b,t,c] = x[b,t,c] + bias[c] + sum_{k=0..3} w[c,k] * x[b, t+k-3, c]
// x: (B=4, T=4096, C=2048) fp32, row-major. weight: (C,4). bias: (C,).
//
// Best replicated: R3 = S=16, lb(128,9), default reads, __stcs stores:
//   regs 56, occ 49.6%, kernel 38.2-39.1us (2 runs), dur_us 47.1.
// Session laws: no cache hints on reads (.cs/.cg regress 1-6us via lost load
//   batching); no reg-diet; occ>~50% regresses.
// R15/R16: isolate S=8 with the EXACT R3 recipe (R8's S=8 was confounded with
//   .cs reads). Halves T_CTA -> smaller drain tail; 8192 CTAs -> finer
//   balance; halo rises to 37.5% of reads but those are adjacent-strip L2 hits.
//   (R16 = resubmit: container infra failure, no measurement obtained.)

#define BB 4
#define TT 4096
#define CC 2048
#define CV (CC / 4)       // 512 float4 channel-vectors per row
#define S  8              // timesteps per block strip
#define TPB 128           // threads per block (covers 128 cvecs)

__global__ __launch_bounds__(TPB, 9) void canonconv_kernel(
    const float* __restrict__ x,
    const float* __restrict__ w,      // (C, 4)
    const float* __restrict__ bias,   // (C,)
    float* __restrict__ out)
{
    const int cvec = blockIdx.y * TPB + threadIdx.x;   // 0..511
    const int c    = cvec * 4;
    const int b    = blockIdx.z;
    const int t0   = blockIdx.x * S;

    const float4* __restrict__ x4 = reinterpret_cast<const float4*>(x);
    float4* __restrict__ o4       = reinterpret_cast<float4*>(out);

    // per-channel weight rows: wr[j] = (w[c+j,0..3])
    const float4* __restrict__ w4 = reinterpret_cast<const float4*>(w);
    const float4 wr0 = w4[c + 0];
    const float4 wr1 = w4[c + 1];
    const float4 wr2 = w4[c + 2];
    const float4 wr3 = w4[c + 3];
    const float4 bi  = reinterpret_cast<const float4*>(bias)[cvec];

    // max index 4*4096*512 = 8.4M float4s -> fits int
    int idx = (b * TT + t0) * CV + cvec;

    const float4 zero = make_float4(0.f, 0.f, 0.f, 0.f);
    // sliding window: x at t0-3, t0-2, t0-1 (t0 is a multiple of S).
    // Default caching: previous strip's freshest rows -> L2 hits here.
    float4 xm3 = (t0 >= 3) ? x4[idx - 3 * CV] : zero;
    float4 xm2 = (t0 >= 2) ? x4[idx - 2 * CV] : zero;
    float4 xm1 = (t0 >= 1) ? x4[idx - 1 * CV] : zero;

#pragma unroll
    for (int i = 0; i < S; i++) {
        const float4 xc = x4[idx];
        float4 r;
        r.x = fmaf(xm3.x, wr0.x, fmaf(xm2.x, wr0.y, fmaf(xm1.x, wr0.z, fmaf(xc.x, wr0.w, xc.x + bi.x))));
        r.y = fmaf(xm3.y, wr1.x, fmaf(xm2.y, wr1.y, fmaf(xm1.y, wr1.z, fmaf(xc.y, wr1.w, xc.y + bi.y))));
        r.z = fmaf(xm3.z, wr2.x, fmaf(xm2.z, wr2.y, fmaf(xm1.z, wr2.z, fmaf(xc.z, wr2.w, xc.z + bi.z))));
        r.w = fmaf(xm3.w, wr3.x, fmaf(xm2.w, wr3.y, fmaf(xm1.w, wr3.z, fmaf(xc.w, wr3.w, xc.w + bi.w))));
        __stcs(&o4[idx], r);   // write-once output: streaming store
        xm3 = xm2; xm2 = xm1; xm1 = xc;
        idx += CV;
    }
}

extern "C" void kernel_launch(void* const* d_in, const int* in_sizes, int n_in,
                              void* d_out, int out_size)
{
    const float* x    = (const float*)d_in[0];
    const float* w    = (const float*)d_in[1];
    const float* bias = (const float*)d_in[2];
    float* out        = (float*)d_out;

    dim3 grid(TT / S, CV / TPB, BB);   // (512, 4, 4) = 8192 CTAs
    dim3 block(TPB);
    canonconv_kernel<<<grid, block>>>(x, w, bias, out);
}